// round 7
// baseline (speedup 1.0000x reference)
#include <cuda_runtime.h>
#include <cuda_fp16.h>
#include <math.h>
#include <stdint.h>

#define BATCH 16
#define CIN   128
#define LIN   8192
#define LOUT  16384
#define COUT  128
#define NMT   128                // original-m per CTA tile (-> 256 outputs)
#define NT    (LIN / NMT)        // 64
#define KTOT  768
#define NCHUNK 12                // chunks of K=64 (32 j's, tap-major)
#define PA    72                 // A smem pitch (halves)
#define PB    136                // B smem pitch (halves)
#define PX    136                // x tile pitch (floats)
#define PM    264                // epilogue staging pitch (halves)

// ---------------- scratch ----------------
__device__ __half g_Ae[COUT * KTOT];
__device__ __half g_Ao[COUT * KTOT];
__device__ __half g_mid[(size_t)BATCH * COUT * LOUT];
__device__ float  g_psum  [BATCH * NT * COUT];
__device__ float  g_psumsq[BATCH * NT * COUT];

// ---------------- smem byte offsets ----------------
#define OFF_X   0                        // 128*136*4 = 69632
#define OFF_A   69632
#define A_BUF_STRIDE 36864
#define A_PAR_STRIDE 18432
#define OFF_B   143360                   // B: 2 buf * 96*PB*2 = 52224; epilogue staging reuses
#define B_BUF_STRIDE 26112               // 96 rows * 136 * 2
#define B_ODD_OFF (32 * PB * 2)          // odd parity starts at block1
#define OFF_WS  212992
#define OFF_WSQ 215040
#define SM_TOTAL 217088

// ---------------- PTX helpers (family-portable) ----------------
__device__ __forceinline__ uint32_t smem_u32(const void* p) {
    uint32_t a;
    asm("{ .reg .u64 t; cvta.to.shared.u64 t, %1; cvt.u32.u64 %0, t; }" : "=r"(a) : "l"(p));
    return a;
}
#define CP_ASYNC16(dst, src) \
    asm volatile("cp.async.cg.shared.global [%0], [%1], 16;" :: "r"(dst), "l"(src) : "memory")
#define CP_COMMIT() asm volatile("cp.async.commit_group;" ::: "memory")
#define CP_WAIT(n)  asm volatile("cp.async.wait_group %0;" :: "n"(n) : "memory")

__device__ __forceinline__ void ldsm_x4(uint32_t* r, uint32_t addr) {
    asm volatile("ldmatrix.sync.aligned.m8n8.x4.shared.b16 {%0,%1,%2,%3}, [%4];"
        : "=r"(r[0]), "=r"(r[1]), "=r"(r[2]), "=r"(r[3]) : "r"(addr));
}
__device__ __forceinline__ void ldsm_x4t(uint32_t* r, uint32_t addr) {
    asm volatile("ldmatrix.sync.aligned.m8n8.x4.trans.shared.b16 {%0,%1,%2,%3}, [%4];"
        : "=r"(r[0]), "=r"(r[1]), "=r"(r[2]), "=r"(r[3]) : "r"(addr));
}
__device__ __forceinline__ void mma16816(float* d, const uint32_t* a, uint32_t b0, uint32_t b1) {
    asm volatile("mma.sync.aligned.m16n8k16.row.col.f32.f16.f16.f32 "
        "{%0,%1,%2,%3}, {%4,%5,%6,%7}, {%8,%9}, {%0,%1,%2,%3};"
        : "+f"(d[0]), "+f"(d[1]), "+f"(d[2]), "+f"(d[3])
        : "r"(a[0]), "r"(a[1]), "r"(a[2]), "r"(a[3]), "r"(b0), "r"(b1));
}
__device__ __forceinline__ uint32_t pk(float a, float b) {
    __half2 h = __floats2half2_rn(a, b);
    return *(uint32_t*)&h;
}

// ---------------------------------------------------------------------------
// Kernel 1: fold W into fp16 even/odd weight images, tap-major K per chunk:
//   chunk c covers j in [32c, 32c+32); k = c*64 + tap*32 + jl
//   even: tap0 = w0 (pairs p[m-1]),  tap1 = w1+w2 (pairs p[m])
//   odd:  tap0 = w0+w1 (pairs p[m]), tap1 = w2   (pairs p[m+1])
// ---------------------------------------------------------------------------
__global__ void prep_weights(const float* __restrict__ W) {
    int idx = blockIdx.x * blockDim.x + threadIdx.x;
    if (idx >= COUT * 384) return;
    int co = idx / 384, j = idx % 384;
    int c = j >> 5, jl = j & 31;
    const float* wp = W + (size_t)idx * 3;
    float w0 = wp[0], w1 = wp[1], w2 = wp[2];
    int base = co * KTOT + c * 64 + jl;
    g_Ae[base]      = __float2half_rn(w0);
    g_Ae[base + 32] = __float2half_rn(w1 + w2);
    g_Ao[base]      = __float2half_rn(w0 + w1);
    g_Ao[base + 32] = __float2half_rn(w2);
}

// ---------------------------------------------------------------------------
// B-build for chunk c1: 96 rows = [block0: p(m-1) | block1: p(m) | block2: p(m+1)]
// ---------------------------------------------------------------------------
__device__ __forceinline__ void buildB(char* smem, int c1, int tid) {
    const int buf = c1 & 1;
    const int q   = c1 >> 2;
    const int jl  = tid >> 4, oct = tid & 15;
    const int ci  = ((c1 & 3) << 5) + jl;
    const int i0  = oct << 3;
    const float4* xr = (const float4*)(smem + OFF_X + (size_t)ci * PX * 4) + (i0 >> 2);
    float4 F0 = xr[0], F1 = xr[1], F2 = xr[2], F3 = xr[3];
    float v0 = F0.w, v1 = F1.x, v2 = F1.y, v3 = F1.z, v4 = F1.w,
          v5 = F2.x, v6 = F2.y, v7 = F2.z, v8 = F2.w, v9 = F3.x;
    if (q == 1) {
        v0 *= v0; v1 *= v1; v2 *= v2; v3 *= v3; v4 *= v4;
        v5 *= v5; v6 *= v6; v7 *= v7; v8 *= v8; v9 *= v9;
    } else if (q == 2) {
        v0 = v0*v0*v0; v1 = v1*v1*v1; v2 = v2*v2*v2; v3 = v3*v3*v3; v4 = v4*v4*v4;
        v5 = v5*v5*v5; v6 = v6*v6*v6; v7 = v7*v7*v7; v8 = v8*v8*v8; v9 = v9*v9*v9;
    }
    uint32_t P0 = pk(v0, v1), P1 = pk(v2, v3), P2 = pk(v4, v5), P3 = pk(v6, v7), P4 = pk(v8, v9);
    uint32_t Q0 = pk(v1, v2), Q1 = pk(v3, v4), Q2 = pk(v5, v6), Q3 = pk(v7, v8);
    char* base = smem + OFF_B + buf * B_BUF_STRIDE + (size_t)(jl * PB + i0) * 2;
    *(uint4*)(base)                    = make_uint4(P0, P1, P2, P3);   // p[m-1]
    *(uint4*)(base + 32 * PB * 2)      = make_uint4(Q0, Q1, Q2, Q3);   // p[m]
    *(uint4*)(base + 64 * PB * 2)      = make_uint4(P1, P2, P3, P4);   // p[m+1]
}

// ---------------------------------------------------------------------------
// Kernel 2: parity-split HMMA conv. Grid (NT, BATCH), 512 threads = 16 warps.
// ---------------------------------------------------------------------------
__global__ __launch_bounds__(512, 1)
void conv_kernel(const float* __restrict__ x,
                 const float* __restrict__ bias) {
    extern __shared__ char smem[];
    const uint32_t sb = smem_u32(smem);
    const int b    = blockIdx.y;
    const int tile = blockIdx.x;
    const int m0   = tile * NMT;
    const int tid  = threadIdx.x;
    const int lane = tid & 31;
    const int w    = tid >> 5;
    const int par   = w >> 3;
    const int cs    = (w >> 1) & 3;
    const int mb    = w & 1;
    const int co0   = cs * 32;
    const int mbase = mb * 64;

    const float* xb = x + (size_t)b * CIN * LIN;

    // ---- prologue: cp.async x-tile interior + A[0] ----
    #pragma unroll
    for (int t = 0; t < 8; t++) {
        int idx = tid + t * 512;
        int r = idx >> 5, tq = idx & 31;
        uint32_t dst = sb + OFF_X + (uint32_t)((r * PX + 4 + tq * 4) * 4);
        const float* src = xb + (size_t)r * LIN + m0 + tq * 4;
        CP_ASYNC16(dst, src);
    }
    #pragma unroll
    for (int t = 0; t < 4; t++) {
        int idx = tid + t * 512;
        int p2 = idx >> 10, r = (idx >> 3) & 127, cq = idx & 7;
        uint32_t dst = sb + OFF_A + p2 * A_PAR_STRIDE + (uint32_t)(r * PA * 2 + cq * 16);
        const __half* src = (p2 ? g_Ao : g_Ae) + (size_t)r * KTOT + cq * 8;
        CP_ASYNC16(dst, src);
    }
    CP_COMMIT();
    if (tid < 256) {
        int ci = tid >> 1, side = tid & 1;
        int pos = side ? (m0 + NMT) : (m0 - 1);
        int col = side ? 132 : 3;
        float v = (pos >= 0 && pos < LIN) ? xb[(size_t)ci * LIN + pos] : 0.f;
        *(float*)(smem + OFF_X + (size_t)(ci * PX + col) * 4) = v;
    }
    CP_WAIT(0);
    __syncthreads();
    buildB(smem, 0, tid);

    float acc[2][8][4];
    #pragma unroll
    for (int mt = 0; mt < 2; mt++)
        #pragma unroll
        for (int nt = 0; nt < 8; nt++)
            #pragma unroll
            for (int r = 0; r < 4; r++) acc[mt][nt][r] = 0.f;

    const uint32_t aRow = lane & 15, aColq = lane >> 4;
    const uint32_t a_off = (uint32_t)(par * A_PAR_STRIDE + ((co0 + aRow) * PA + aColq * 8) * 2);
    const uint32_t b_off = (uint32_t)(par * B_ODD_OFF + (aRow * PB + mbase + aColq * 8) * 2);

    for (int c = 0; c < NCHUNK; c++) {
        CP_WAIT(0);
        __syncthreads();
        if (c + 1 < NCHUNK) {
            #pragma unroll
            for (int t = 0; t < 4; t++) {
                int idx = tid + t * 512;
                int p2 = idx >> 10, r = (idx >> 3) & 127, cq = idx & 7;
                uint32_t dst = sb + OFF_A + ((c + 1) & 1) * A_BUF_STRIDE
                             + p2 * A_PAR_STRIDE + (uint32_t)(r * PA * 2 + cq * 16);
                const __half* src = (p2 ? g_Ao : g_Ae) + (size_t)r * KTOT + (c + 1) * 64 + cq * 8;
                CP_ASYNC16(dst, src);
            }
            CP_COMMIT();
        }
        const uint32_t aB = sb + OFF_A + (c & 1) * A_BUF_STRIDE + a_off;
        const uint32_t bB = sb + OFF_B + (c & 1) * B_BUF_STRIDE + b_off;

        // fully double-buffered fragments (A and B one k-step ahead)
        uint32_t af[2][2][4];            // [buf][mt][reg]
        uint32_t bf[2][4][4];            // [buf][nb][reg]
        ldsm_x4(af[0][0], aB);
        ldsm_x4(af[0][1], aB + 16 * PA * 2);
        #pragma unroll
        for (int nb = 0; nb < 4; nb++) ldsm_x4t(bf[0][nb], bB + nb * 32);

        #pragma unroll
        for (int ks = 0; ks < 4; ks++) {
            const int cur = ks & 1;
            if (ks < 3) {
                uint32_t ak = aB + (ks + 1) * 32;
                ldsm_x4(af[cur ^ 1][0], ak);
                ldsm_x4(af[cur ^ 1][1], ak + 16 * PA * 2);
                uint32_t bk = bB + (ks + 1) * 16 * PB * 2;
                #pragma unroll
                for (int nb = 0; nb < 4; nb++) ldsm_x4t(bf[cur ^ 1][nb], bk + nb * 32);
            }
            #pragma unroll
            for (int mt = 0; mt < 2; mt++)
                #pragma unroll
                for (int nt = 0; nt < 8; nt++) {
                    int nb = nt >> 1, pr = (nt & 1) * 2;
                    mma16816(acc[mt][nt], af[cur][mt], bf[cur][nb][pr], bf[cur][nb][pr + 1]);
                }
            if (ks == 1 && c + 1 < NCHUNK) buildB(smem, c + 1, tid);
        }
    }

    // ---- epilogue: stage fp16 tile in SMEM (reuse B area), stats ----
    __syncthreads();
    __half* sMid = (__half*)(smem + OFF_B);
    float* sWS  = (float*)(smem + OFF_WS);
    float* sWSq = (float*)(smem + OFF_WSQ);
    #pragma unroll
    for (int mt = 0; mt < 2; mt++) {
        #pragma unroll
        for (int half = 0; half < 2; half++) {
            int co = co0 + mt * 16 + (lane >> 2) + half * 8;
            float bv = __ldg(&bias[co]);
            float s = 0.f, ss = 0.f;
            #pragma unroll
            for (int nt = 0; nt < 8; nt++) {
                float v0 = acc[mt][nt][half * 2 + 0] + bv;
                float v1 = acc[mt][nt][half * 2 + 1] + bv;
                int m = mbase + nt * 8 + (lane & 3) * 2;
                sMid[co * PM + 2 * m + par]       = __float2half_rn(v0);
                sMid[co * PM + 2 * (m + 1) + par] = __float2half_rn(v1);
                s  += v0 + v1;
                ss += v0 * v0 + v1 * v1;
            }
            s  += __shfl_xor_sync(0xffffffffu, s, 1);
            s  += __shfl_xor_sync(0xffffffffu, s, 2);
            ss += __shfl_xor_sync(0xffffffffu, ss, 1);
            ss += __shfl_xor_sync(0xffffffffu, ss, 2);
            if ((lane & 3) == 0) {
                int cl = mt * 16 + (lane >> 2) + half * 8;
                sWS [w * 32 + cl] = s;
                sWSq[w * 32 + cl] = ss;
            }
        }
    }
    __syncthreads();
    if (tid < 128) {
        int co = tid, cs2 = co >> 5, cl = co & 31;
        float s = 0.f, ss = 0.f;
        #pragma unroll
        for (int p2 = 0; p2 < 2; p2++)
            #pragma unroll
            for (int mb2 = 0; mb2 < 2; mb2++) {
                int w2 = p2 * 8 + cs2 * 2 + mb2;
                s  += sWS [w2 * 32 + cl];
                ss += sWSq[w2 * 32 + cl];
            }
        int pidx = (b * NT + tile) * COUT + co;
        g_psum[pidx]   = s;
        g_psumsq[pidx] = ss;
    }
    #pragma unroll
    for (int t = 0; t < 8; t++) {
        int i = tid + t * 512;
        int row = i >> 5, cq = i & 31;
        uint4 v = *(uint4*)(sMid + row * PM + cq * 8);
        *(uint4*)(g_mid + (size_t)(b * COUT + row) * LOUT + 2 * m0 + cq * 8) = v;
    }
}

// ---------------------------------------------------------------------------
// Kernel 3: fused stats-reduce + normalize + tanh. One block per (b,co) row.
// ---------------------------------------------------------------------------
__global__ __launch_bounds__(256, 8)
void norm_fused(float* __restrict__ out) {
    __shared__ float sstat[2];
    const int row = blockIdx.x;          // b*COUT + co
    const int tid = threadIdx.x;
    if (tid < 32) {
        int b = row >> 7, co = row & 127;
        float s = 0.f, ss = 0.f;
        #pragma unroll
        for (int h = 0; h < 2; h++) {
            int t = tid + h * 32;
            int p = (b * NT + t) * COUT + co;
            s  += g_psum[p];
            ss += g_psumsq[p];
        }
        #pragma unroll
        for (int off = 16; off > 0; off >>= 1) {
            s  += __shfl_xor_sync(0xffffffffu, s, off);
            ss += __shfl_xor_sync(0xffffffffu, ss, off);
        }
        if (tid == 0) {
            double mean = (double)s / (double)LOUT;
            double var  = (double)ss / (double)LOUT - mean * mean;
            sstat[0] = (float)mean;
            sstat[1] = (float)(1.0 / sqrt(var + 1e-5));
        }
    }
    __syncthreads();
    const float mean = sstat[0], rstd = sstat[1];
    const uint4* m8 = (const uint4*)(g_mid + (size_t)row * LOUT);
    float4* o4 = (float4*)(out + (size_t)row * LOUT);
    #pragma unroll
    for (int i = 0; i < 8; i++) {
        int idx = tid + i * 256;         // 2048 uint4 per row
        uint4 v = m8[idx];
        float2 a0 = __half22float2(*(__half2*)&v.x);
        float2 a1 = __half22float2(*(__half2*)&v.y);
        float2 a2 = __half22float2(*(__half2*)&v.z);
        float2 a3 = __half22float2(*(__half2*)&v.w);
        float4 r0, r1;
        r0.x = tanhf((a0.x - mean) * rstd);
        r0.y = tanhf((a0.y - mean) * rstd);
        r0.z = tanhf((a1.x - mean) * rstd);
        r0.w = tanhf((a1.y - mean) * rstd);
        r1.x = tanhf((a2.x - mean) * rstd);
        r1.y = tanhf((a2.y - mean) * rstd);
        r1.z = tanhf((a3.x - mean) * rstd);
        r1.w = tanhf((a3.y - mean) * rstd);
        o4[idx * 2 + 0] = r0;
        o4[idx * 2 + 1] = r1;
    }
}

// ---------------------------------------------------------------------------
extern "C" void kernel_launch(void* const* d_in, const int* in_sizes, int n_in,
                              void* d_out, int out_size) {
    const float* x    = (const float*)d_in[0];
    const float* W    = (const float*)d_in[1];
    const float* bias = (const float*)d_in[2];
    float* out = (float*)d_out;

    cudaFuncSetAttribute(conv_kernel,
                         cudaFuncAttributeMaxDynamicSharedMemorySize, SM_TOTAL);

    prep_weights<<<(COUT * 384 + 255) / 256, 256>>>(W);
    conv_kernel<<<dim3(NT, BATCH), 512, SM_TOTAL>>>(x, bias);
    norm_fused<<<BATCH * COUT, 256>>>(out);
}

// round 8
// speedup vs baseline: 1.0639x; 1.0639x over previous
#include <cuda_runtime.h>
#include <cuda_fp16.h>
#include <math.h>
#include <stdint.h>

#define BATCH 16
#define CIN   128
#define LIN   8192
#define LOUT  16384
#define COUT  128
#define NMT   128                // original-m per CTA tile (-> 256 outputs)
#define NT    (LIN / NMT)        // 64
#define KTOT  768
#define NCHUNK 12                // chunks of K=64 (32 j's, tap-major)
#define PA    72                 // A smem pitch (halves)
#define PB    136                // B smem pitch (halves)
#define PX    136                // x tile pitch (floats)
#define PM    264                // epilogue staging pitch (halves)

// ---------------- scratch ----------------
__device__ __half g_Ae[COUT * KTOT];
__device__ __half g_Ao[COUT * KTOT];
__device__ __half g_mid[(size_t)BATCH * COUT * LOUT];
__device__ float  g_psum  [BATCH * NT * COUT];
__device__ float  g_psumsq[BATCH * NT * COUT];

// ---------------- smem byte offsets ----------------
#define OFF_X   0                        // 128*136*4 = 69632
#define OFF_A   69632
#define A_BUF_STRIDE 36864
#define A_PAR_STRIDE 18432
#define OFF_B   143360                   // B: 2 buf * 96*PB*2 = 52224; epilogue reuses
#define B_BUF_STRIDE 26112               // 96 rows * 136 * 2
#define B_ODD_OFF (32 * PB * 2)          // odd parity window starts at block1
#define OFF_WS  212992
#define OFF_WSQ 215040
#define SM_TOTAL 217088

// ---------------- PTX helpers (family-portable) ----------------
__device__ __forceinline__ uint32_t smem_u32(const void* p) {
    uint32_t a;
    asm("{ .reg .u64 t; cvta.to.shared.u64 t, %1; cvt.u32.u64 %0, t; }" : "=r"(a) : "l"(p));
    return a;
}
#define CP_ASYNC16(dst, src) \
    asm volatile("cp.async.cg.shared.global [%0], [%1], 16;" :: "r"(dst), "l"(src) : "memory")
#define CP_COMMIT() asm volatile("cp.async.commit_group;" ::: "memory")
#define CP_WAIT(n)  asm volatile("cp.async.wait_group %0;" :: "n"(n) : "memory")

__device__ __forceinline__ void ldsm_x4(uint32_t* r, uint32_t addr) {
    asm volatile("ldmatrix.sync.aligned.m8n8.x4.shared.b16 {%0,%1,%2,%3}, [%4];"
        : "=r"(r[0]), "=r"(r[1]), "=r"(r[2]), "=r"(r[3]) : "r"(addr));
}
__device__ __forceinline__ void ldsm_x4t(uint32_t* r, uint32_t addr) {
    asm volatile("ldmatrix.sync.aligned.m8n8.x4.trans.shared.b16 {%0,%1,%2,%3}, [%4];"
        : "=r"(r[0]), "=r"(r[1]), "=r"(r[2]), "=r"(r[3]) : "r"(addr));
}
__device__ __forceinline__ void mma16816(float* d, const uint32_t* a, uint32_t b0, uint32_t b1) {
    asm volatile("mma.sync.aligned.m16n8k16.row.col.f32.f16.f16.f32 "
        "{%0,%1,%2,%3}, {%4,%5,%6,%7}, {%8,%9}, {%0,%1,%2,%3};"
        : "+f"(d[0]), "+f"(d[1]), "+f"(d[2]), "+f"(d[3])
        : "r"(a[0]), "r"(a[1]), "r"(a[2]), "r"(a[3]), "r"(b0), "r"(b1));
}
__device__ __forceinline__ uint32_t pk(float a, float b) {
    __half2 h = __floats2half2_rn(a, b);
    return *(uint32_t*)&h;
}

// ---------------------------------------------------------------------------
// Kernel 1: fold W into fp16 even/odd weight images, tap-major K per chunk:
//   chunk c covers j in [32c, 32c+32); k = c*64 + tap*32 + jl
//   even: tap0 = w0 (pairs p[m-1]),  tap1 = w1+w2 (pairs p[m])
//   odd:  tap0 = w0+w1 (pairs p[m]), tap1 = w2   (pairs p[m+1])
// ---------------------------------------------------------------------------
__global__ void prep_weights(const float* __restrict__ W) {
    int idx = blockIdx.x * blockDim.x + threadIdx.x;
    if (idx >= COUT * 384) return;
    int co = idx / 384, j = idx % 384;
    int c = j >> 5, jl = j & 31;
    const float* wp = W + (size_t)idx * 3;
    float w0 = wp[0], w1 = wp[1], w2 = wp[2];
    int base = co * KTOT + c * 64 + jl;
    g_Ae[base]      = __float2half_rn(w0);
    g_Ae[base + 32] = __float2half_rn(w1 + w2);
    g_Ao[base]      = __float2half_rn(w0 + w1);
    g_Ao[base + 32] = __float2half_rn(w2);
}

// ---------------------------------------------------------------------------
// B-build for chunk c1: 96 rows = [p(m-1) | p(m) | p(m+1)] blocks of 32 j-rows
// ---------------------------------------------------------------------------
__device__ __forceinline__ void buildB(char* smem, int c1, int tid) {
    const int buf = c1 & 1;
    const int q   = c1 >> 2;
    const int jl  = tid >> 4, oct = tid & 15;
    const int ci  = ((c1 & 3) << 5) + jl;
    const int i0  = oct << 3;
    const float4* xr = (const float4*)(smem + OFF_X + (size_t)ci * PX * 4) + (i0 >> 2);
    float4 F0 = xr[0], F1 = xr[1], F2 = xr[2], F3 = xr[3];
    float v0 = F0.w, v1 = F1.x, v2 = F1.y, v3 = F1.z, v4 = F1.w,
          v5 = F2.x, v6 = F2.y, v7 = F2.z, v8 = F2.w, v9 = F3.x;
    if (q == 1) {
        v0 *= v0; v1 *= v1; v2 *= v2; v3 *= v3; v4 *= v4;
        v5 *= v5; v6 *= v6; v7 *= v7; v8 *= v8; v9 *= v9;
    } else if (q == 2) {
        v0 = v0*v0*v0; v1 = v1*v1*v1; v2 = v2*v2*v2; v3 = v3*v3*v3; v4 = v4*v4*v4;
        v5 = v5*v5*v5; v6 = v6*v6*v6; v7 = v7*v7*v7; v8 = v8*v8*v8; v9 = v9*v9*v9;
    }
    uint32_t P0 = pk(v0, v1), P1 = pk(v2, v3), P2 = pk(v4, v5), P3 = pk(v6, v7), P4 = pk(v8, v9);
    uint32_t Q0 = pk(v1, v2), Q1 = pk(v3, v4), Q2 = pk(v5, v6), Q3 = pk(v7, v8);
    char* base = smem + OFF_B + buf * B_BUF_STRIDE + (size_t)(jl * PB + i0) * 2;
    *(uint4*)(base)               = make_uint4(P0, P1, P2, P3);   // p[m-1]
    *(uint4*)(base + 32 * PB * 2) = make_uint4(Q0, Q1, Q2, Q3);   // p[m]
    *(uint4*)(base + 64 * PB * 2) = make_uint4(P1, P2, P3, P4);   // p[m+1]
}

// ---------------------------------------------------------------------------
// Kernel 2: parity-split HMMA conv. Grid (NT, BATCH), 512 threads = 16 warps.
// Warp = one parity, 32co x 64m. A frags single-buffered, B frags double.
// ---------------------------------------------------------------------------
__global__ __launch_bounds__(512, 1)
void conv_kernel(const float* __restrict__ x,
                 const float* __restrict__ bias) {
    extern __shared__ char smem[];
    const uint32_t sb = smem_u32(smem);
    const int b    = blockIdx.y;
    const int tile = blockIdx.x;
    const int m0   = tile * NMT;
    const int tid  = threadIdx.x;
    const int lane = tid & 31;
    const int w    = tid >> 5;
    const int par   = w >> 3;
    const int cs    = (w >> 1) & 3;
    const int mb    = w & 1;
    const int co0   = cs * 32;
    const int mbase = mb * 64;

    const float* xb = x + (size_t)b * CIN * LIN;

    // ---- prologue: cp.async x-tile interior + A[0] ----
    #pragma unroll
    for (int t = 0; t < 8; t++) {
        int idx = tid + t * 512;
        int r = idx >> 5, tq = idx & 31;
        uint32_t dst = sb + OFF_X + (uint32_t)((r * PX + 4 + tq * 4) * 4);
        const float* src = xb + (size_t)r * LIN + m0 + tq * 4;
        CP_ASYNC16(dst, src);
    }
    #pragma unroll
    for (int t = 0; t < 4; t++) {
        int idx = tid + t * 512;
        int p2 = idx >> 10, r = (idx >> 3) & 127, cq = idx & 7;
        uint32_t dst = sb + OFF_A + p2 * A_PAR_STRIDE + (uint32_t)(r * PA * 2 + cq * 16);
        const __half* src = (p2 ? g_Ao : g_Ae) + (size_t)r * KTOT + cq * 8;
        CP_ASYNC16(dst, src);
    }
    CP_COMMIT();
    if (tid < 256) {
        int ci = tid >> 1, side = tid & 1;
        int pos = side ? (m0 + NMT) : (m0 - 1);
        int col = side ? 132 : 3;
        float v = (pos >= 0 && pos < LIN) ? xb[(size_t)ci * LIN + pos] : 0.f;
        *(float*)(smem + OFF_X + (size_t)(ci * PX + col) * 4) = v;
    }
    CP_WAIT(0);
    __syncthreads();
    buildB(smem, 0, tid);

    float acc[2][8][4];
    #pragma unroll
    for (int mt = 0; mt < 2; mt++)
        #pragma unroll
        for (int nt = 0; nt < 8; nt++)
            #pragma unroll
            for (int r = 0; r < 4; r++) acc[mt][nt][r] = 0.f;

    const uint32_t aRow = lane & 15, aColq = lane >> 4;
    const uint32_t a_off = (uint32_t)(par * A_PAR_STRIDE + ((co0 + aRow) * PA + aColq * 8) * 2);
    const uint32_t b_off = (uint32_t)(par * B_ODD_OFF + (aRow * PB + mbase + aColq * 8) * 2);

    for (int c = 0; c < NCHUNK; c++) {
        CP_WAIT(0);
        __syncthreads();
        if (c + 1 < NCHUNK) {
            #pragma unroll
            for (int t = 0; t < 4; t++) {
                int idx = tid + t * 512;
                int p2 = idx >> 10, r = (idx >> 3) & 127, cq = idx & 7;
                uint32_t dst = sb + OFF_A + ((c + 1) & 1) * A_BUF_STRIDE
                             + p2 * A_PAR_STRIDE + (uint32_t)(r * PA * 2 + cq * 16);
                const __half* src = (p2 ? g_Ao : g_Ae) + (size_t)r * KTOT + (c + 1) * 64 + cq * 8;
                CP_ASYNC16(dst, src);
            }
            CP_COMMIT();
        }
        const uint32_t aB = sb + OFF_A + (c & 1) * A_BUF_STRIDE + a_off;
        const uint32_t bB = sb + OFF_B + (c & 1) * B_BUF_STRIDE + b_off;

        uint32_t af[2][4];               // A frags, single-buffered
        uint32_t bf[2][4][4];            // B frags, double-buffered
        #pragma unroll
        for (int nb = 0; nb < 4; nb++) ldsm_x4t(bf[0][nb], bB + nb * 32);

        #pragma unroll
        for (int ks = 0; ks < 4; ks++) {
            const int cur = ks & 1;
            ldsm_x4(af[0], aB + ks * 32);
            ldsm_x4(af[1], aB + ks * 32 + 16 * PA * 2);
            if (ks < 3) {
                uint32_t bk = bB + (ks + 1) * 16 * PB * 2;
                #pragma unroll
                for (int nb = 0; nb < 4; nb++) ldsm_x4t(bf[cur ^ 1][nb], bk + nb * 32);
            }
            #pragma unroll
            for (int mt = 0; mt < 2; mt++)
                #pragma unroll
                for (int nt = 0; nt < 8; nt++) {
                    int nb = nt >> 1, pr = (nt & 1) * 2;
                    mma16816(acc[mt][nt], af[mt], bf[cur][nb][pr], bf[cur][nb][pr + 1]);
                }
            if (ks == 1 && c + 1 < NCHUNK) buildB(smem, c + 1, tid);
        }
    }

    // ---- epilogue: stage fp16 tile in SMEM (reuse B area), stats ----
    __syncthreads();
    __half* sMid = (__half*)(smem + OFF_B);
    float* sWS  = (float*)(smem + OFF_WS);
    float* sWSq = (float*)(smem + OFF_WSQ);
    #pragma unroll
    for (int mt = 0; mt < 2; mt++) {
        #pragma unroll
        for (int half = 0; half < 2; half++) {
            int co = co0 + mt * 16 + (lane >> 2) + half * 8;
            float bv = __ldg(&bias[co]);
            float s = 0.f, ss = 0.f;
            #pragma unroll
            for (int nt = 0; nt < 8; nt++) {
                float v0 = acc[mt][nt][half * 2 + 0] + bv;
                float v1 = acc[mt][nt][half * 2 + 1] + bv;
                int m = mbase + nt * 8 + (lane & 3) * 2;
                sMid[co * PM + 2 * m + par]       = __float2half_rn(v0);
                sMid[co * PM + 2 * (m + 1) + par] = __float2half_rn(v1);
                s  += v0 + v1;
                ss += v0 * v0 + v1 * v1;
            }
            s  += __shfl_xor_sync(0xffffffffu, s, 1);
            s  += __shfl_xor_sync(0xffffffffu, s, 2);
            ss += __shfl_xor_sync(0xffffffffu, ss, 1);
            ss += __shfl_xor_sync(0xffffffffu, ss, 2);
            if ((lane & 3) == 0) {
                int cl = mt * 16 + (lane >> 2) + half * 8;
                sWS [w * 32 + cl] = s;
                sWSq[w * 32 + cl] = ss;
            }
        }
    }
    __syncthreads();
    if (tid < 128) {
        int co = tid, cs2 = co >> 5, cl = co & 31;
        float s = 0.f, ss = 0.f;
        #pragma unroll
        for (int p2 = 0; p2 < 2; p2++)
            #pragma unroll
            for (int mb2 = 0; mb2 < 2; mb2++) {
                int w2 = p2 * 8 + cs2 * 2 + mb2;
                s  += sWS [w2 * 32 + cl];
                ss += sWSq[w2 * 32 + cl];
            }
        int pidx = (b * NT + tile) * COUT + co;
        g_psum[pidx]   = s;
        g_psumsq[pidx] = ss;
    }
    #pragma unroll
    for (int t = 0; t < 8; t++) {
        int i = tid + t * 512;
        int row = i >> 5, cq = i & 31;
        uint4 v = *(uint4*)(sMid + row * PM + cq * 8);
        *(uint4*)(g_mid + (size_t)(b * COUT + row) * LOUT + 2 * m0 + cq * 8) = v;
    }
}

// ---------------------------------------------------------------------------
// Kernel 3: fused stats-reduce + normalize + tanh. One block per (b,co) row.
// ---------------------------------------------------------------------------
__global__ __launch_bounds__(256, 8)
void norm_fused(float* __restrict__ out) {
    __shared__ float sstat[2];
    const int row = blockIdx.x;
    const int tid = threadIdx.x;
    if (tid < 32) {
        int b = row >> 7, co = row & 127;
        float s = 0.f, ss = 0.f;
        #pragma unroll
        for (int h = 0; h < 2; h++) {
            int t = tid + h * 32;
            int p = (b * NT + t) * COUT + co;
            s  += g_psum[p];
            ss += g_psumsq[p];
        }
        #pragma unroll
        for (int off = 16; off > 0; off >>= 1) {
            s  += __shfl_xor_sync(0xffffffffu, s, off);
            ss += __shfl_xor_sync(0xffffffffu, ss, off);
        }
        if (tid == 0) {
            double mean = (double)s / (double)LOUT;
            double var  = (double)ss / (double)LOUT - mean * mean;
            sstat[0] = (float)mean;
            sstat[1] = (float)(1.0 / sqrt(var + 1e-5));
        }
    }
    __syncthreads();
    const float mean = sstat[0], rstd = sstat[1];
    const uint4* m8 = (const uint4*)(g_mid + (size_t)row * LOUT);
    float4* o4 = (float4*)(out + (size_t)row * LOUT);
    #pragma unroll
    for (int i = 0; i < 8; i++) {
        int idx = tid + i * 256;
        uint4 v = m8[idx];
        float2 a0 = __half22float2(*(__half2*)&v.x);
        float2 a1 = __half22float2(*(__half2*)&v.y);
        float2 a2 = __half22float2(*(__half2*)&v.z);
        float2 a3 = __half22float2(*(__half2*)&v.w);
        float4 r0, r1;
        r0.x = tanhf((a0.x - mean) * rstd);
        r0.y = tanhf((a0.y - mean) * rstd);
        r0.z = tanhf((a1.x - mean) * rstd);
        r0.w = tanhf((a1.y - mean) * rstd);
        r1.x = tanhf((a2.x - mean) * rstd);
        r1.y = tanhf((a2.y - mean) * rstd);
        r1.z = tanhf((a3.x - mean) * rstd);
        r1.w = tanhf((a3.y - mean) * rstd);
        o4[idx * 2 + 0] = r0;
        o4[idx * 2 + 1] = r1;
    }
}

// ---------------------------------------------------------------------------
extern "C" void kernel_launch(void* const* d_in, const int* in_sizes, int n_in,
                              void* d_out, int out_size) {
    const float* x    = (const float*)d_in[0];
    const float* W    = (const float*)d_in[1];
    const float* bias = (const float*)d_in[2];
    float* out = (float*)d_out;

    cudaFuncSetAttribute(conv_kernel,
                         cudaFuncAttributeMaxDynamicSharedMemorySize, SM_TOTAL);

    prep_weights<<<(COUT * 384 + 255) / 256, 256>>>(W);
    conv_kernel<<<dim3(NT, BATCH), 512, SM_TOTAL>>>(x, bias);
    norm_fused<<<BATCH * COUT, 256>>>(out);
}